// round 16
// baseline (speedup 1.0000x reference)
#include <cuda_runtime.h>
#include <cuda_fp16.h>
#include <math.h>
#include <stdint.h>

#define BATCH 8
#define SEQ   1024
#define CDIM  768
#define NH    12
#define HD    64
#define N3    (3*CDIM)

// Scratch: fp16 payloads stored in uint32 arrays.
__device__ uint32_t g_q  [BATCH*NH*SEQ*HD/2];   // [B,H,T,D] half, pre-scaled 0.125*log2e
__device__ uint32_t g_k  [BATCH*NH*SEQ*HD/2];   // [B,H,T,D] half
__device__ uint32_t g_vT [BATCH*NH*SEQ*HD/2];   // [B,H,D,T] half (transposed)
__device__ uint32_t g_att[BATCH*SEQ*CDIM/2];    // [B,T,C] half
__device__ uint32_t g_xc [BATCH*SEQ*CDIM/2];    // x in half
__device__ uint32_t g_wat[N3*CDIM/2];           // W_attn^T [N3][CDIM] half
__device__ uint32_t g_wpt[CDIM*CDIM/2];         // W_proj^T [CDIM][CDIM] half

// Persistent-queue control (reset by prep each launch/replay)
__device__ int g_ctr;
__device__ int g_qflag[64*18];          // QKV tile flags [bm][bn]
__device__ int g_fflag[BATCH*NH*8];     // flash tile flags [b][h][q]

// Phase-major tile schedule: 1152 QKV, then 768 flash, then 384 proj.
#define NQ 1152
#define NF 768
#define NP 384
#define NTILE (NQ+NF+NP)

// ---------------------------------------------------------------------------
// helpers
// ---------------------------------------------------------------------------
__device__ __forceinline__ uint32_t f2h2(float a, float b) {
    __half2 h = __floats2half2_rn(a, b);
    return *(uint32_t*)&h;
}
__device__ __forceinline__ float ex2f(float x) {
    float r; asm("ex2.approx.f32 %0, %1;" : "=f"(r) : "f"(x)); return r;
}

__device__ __forceinline__ void mma_f16(float* c, const uint32_t* a, const uint32_t* b) {
    asm volatile(
        "mma.sync.aligned.m16n8k16.row.col.f32.f16.f16.f32 "
        "{%0,%1,%2,%3}, {%4,%5,%6,%7}, {%8,%9}, {%0,%1,%2,%3};"
        : "+f"(c[0]), "+f"(c[1]), "+f"(c[2]), "+f"(c[3])
        : "r"(a[0]), "r"(a[1]), "r"(a[2]), "r"(a[3]), "r"(b[0]), "r"(b[1]));
}

__device__ __forceinline__ void ldsm4(uint32_t* r, uint32_t a) {
    asm volatile("ldmatrix.sync.aligned.m8n8.x4.shared.b16 {%0,%1,%2,%3}, [%4];"
        : "=r"(r[0]), "=r"(r[1]), "=r"(r[2]), "=r"(r[3]) : "r"(a));
}

__device__ __forceinline__ void cpa16(uint32_t saddr, const void* gaddr) {
    asm volatile("cp.async.cg.shared.global [%0], [%1], 16;" :: "r"(saddr), "l"(gaddr));
}
__device__ __forceinline__ void cpa_commit() { asm volatile("cp.async.commit_group;"); }
template<int NN> __device__ __forceinline__ void cpa_wait() {
    asm volatile("cp.async.wait_group %0;" :: "n"(NN));
}
__device__ __forceinline__ uint32_t smem_u32(const void* p) {
    return (uint32_t)__cvta_generic_to_shared(p);
}
__device__ __forceinline__ void wait_flag(int* f) {
    while (atomicAdd(f, 0) == 0) { __nanosleep(64); }
}

// softmax constants (log2 domain)
#define QSCALE  0.1803368867f    // 0.125 * log2(e)
#define MASKC  -14.4269504089f   // -10 * log2(e)  (fixed shift, cancels in norm)

// ---------------------------------------------------------------------------
// Merged prep kernel: resets queue state; x->half; weight transposes.
// ---------------------------------------------------------------------------
#define XN4     (BATCH*SEQ*CDIM/4)      // 1572864
#define XBLK    (XN4/256)               // 6144
#define WABLK   ((N3/32)*(CDIM/32))     // 1728
#define WPBLK   ((CDIM/32)*(CDIM/32))   // 576

__device__ __forceinline__ void transpose_body(const float* __restrict__ w, __half* wt,
                                               int K, int N, int bx, int by, int tid)
{
    __shared__ float t[32][33];
    int tx = tid & 31, ty = tid >> 5;   // 32 x 8
    int n0 = bx * 32, k0 = by * 32;
    #pragma unroll
    for (int i = 0; i < 32; i += 8)
        t[ty + i][tx] = w[(size_t)(k0 + ty + i) * N + n0 + tx];
    __syncthreads();
    #pragma unroll
    for (int i = 0; i < 32; i += 8)
        wt[(size_t)(n0 + ty + i) * K + k0 + tx] = __float2half(t[tx][ty + i]);
}

__global__ void prep(const float* __restrict__ x,
                     const float* __restrict__ wa,
                     const float* __restrict__ wp)
{
    int bid = blockIdx.x;
    int tid = threadIdx.x;
    int gi  = bid * 256 + tid;
    if (gi == 0) g_ctr = 0;
    if (gi < 64*18) g_qflag[gi] = 0;
    if (gi < BATCH*NH*8) g_fflag[gi] = 0;
    if (bid < XBLK) {
        float4 v = ((const float4*)x)[gi];
        uint2 u = { f2h2(v.x, v.y), f2h2(v.z, v.w) };
        ((uint2*)g_xc)[gi] = u;
    } else if (bid < XBLK + WABLK) {
        int bb = bid - XBLK;
        transpose_body(wa, (__half*)g_wat, CDIM, N3, bb % (N3/32), bb / (N3/32), tid);
    } else {
        int bb = bid - XBLK - WABLK;
        transpose_body(wp, (__half*)g_wpt, CDIM, CDIM, bb % (CDIM/32), bb / (CDIM/32), tid);
    }
}

// ---------------------------------------------------------------------------
// GEMM tile body (round-14 verbatim): 128x128 out, K=768, 3-stage cp.async.
// MODE 1: A=g_xc, W=g_wat, scatter q(*QSCALE)/k/vT.  MODE 0: A=g_att, W=g_wpt.
// ---------------------------------------------------------------------------
#define LD2 36
#define TW  (128 * LD2)
#define GST 3
#define GNC (CDIM / 64)   // 12 chunks

template<int MODE>
__device__ __forceinline__ void gemm_tile(int bm, int bn,
                                          const float* __restrict__ bias,
                                          float* __restrict__ Cout,
                                          uint32_t* sm, int tid)
{
    const uint32_t* A2 = MODE ? g_xc  : g_att;
    const uint32_t* W2 = MODE ? g_wat : g_wpt;
    const int K2 = CDIM / 2;

    const uint32_t sAs = smem_u32(sm);
    const uint32_t sBs = smem_u32(sm + GST * TW);

    const int warp = tid >> 5;
    const int lane = tid & 31;
    const int wm   = warp & 1;
    const int wn   = warp >> 1;
    const int g    = lane >> 2;
    const int t4   = lane & 3;

    const int lr    = lane & 7;
    const int rowAo = wm * 64 + ((lane >> 3) & 1) * 8 + lr;
    const int colAo = (lane >> 4) * 4;
    const int rowB4 = wn * 32 + lr + ((lane >> 4) & 1) * 8;
    const int colB4 = ((lane >> 3) & 1) * 4;

    float acc[4][4][4];
    #pragma unroll
    for (int mt = 0; mt < 4; mt++)
        #pragma unroll
        for (int nt = 0; nt < 4; nt++)
            #pragma unroll
            for (int i = 0; i < 4; i++) acc[mt][nt][i] = 0.f;

    auto stage = [&](int buf, int k0w) {
        #pragma unroll
        for (int it = 0; it < 4; it++) {
            int i = tid + it * 256;
            int r = i >> 3, c = i & 7;
            cpa16(sAs + (uint32_t)(buf * TW + r * LD2 + c * 4) * 4,
                  &A2[(size_t)(bm + r) * K2 + k0w + c * 4]);
        }
        #pragma unroll
        for (int it = 0; it < 4; it++) {
            int i = tid + it * 256;
            int r = i >> 3, c = i & 7;
            cpa16(sBs + (uint32_t)(buf * TW + r * LD2 + c * 4) * 4,
                  &W2[(size_t)(bn + r) * K2 + k0w + c * 4]);
        }
        cpa_commit();
    };

    stage(0, 0);
    stage(1, 32);

    int buf = 0;
    for (int ck = 0; ck < GNC; ck++) {
        if (ck + 2 < GNC) cpa_wait<1>(); else cpa_wait<0>();   // race-safe tail
        __syncthreads();

        if (ck + 2 < GNC) {
            int nbuf = buf + 2; if (nbuf >= GST) nbuf -= GST;
            stage(nbuf, (ck + 2) * 32);
        }

        const uint32_t bA = sAs + (uint32_t)(buf * TW) * 4;
        const uint32_t bB = sBs + (uint32_t)(buf * TW) * 4;

        uint32_t a[2][4][4], b[2][2][4];
        #pragma unroll
        for (int mt = 0; mt < 4; mt++)
            ldsm4(a[0][mt], bA + (uint32_t)((rowAo + mt * 16) * LD2 + colAo) * 4);
        #pragma unroll
        for (int nt2 = 0; nt2 < 2; nt2++)
            ldsm4(b[0][nt2], bB + (uint32_t)((rowB4 + nt2 * 16) * LD2 + colB4) * 4);

        #pragma unroll
        for (int ks = 0; ks < 4; ks++) {
            const int cur = ks & 1;
            if (ks < 3) {
                const int kk2n = (ks + 1) * 8;
                #pragma unroll
                for (int mt = 0; mt < 4; mt++)
                    ldsm4(a[cur ^ 1][mt],
                          bA + (uint32_t)((rowAo + mt * 16) * LD2 + kk2n + colAo) * 4);
                #pragma unroll
                for (int nt2 = 0; nt2 < 2; nt2++)
                    ldsm4(b[cur ^ 1][nt2],
                          bB + (uint32_t)((rowB4 + nt2 * 16) * LD2 + kk2n + colB4) * 4);
            }
            #pragma unroll
            for (int mt = 0; mt < 4; mt++)
                #pragma unroll
                for (int nt = 0; nt < 4; nt++)
                    mma_f16(acc[mt][nt], a[cur][mt], &b[cur][nt >> 1][(nt & 1) * 2]);
        }

        buf++; if (buf >= GST) buf = 0;
    }

    #pragma unroll
    for (int mt = 0; mt < 4; mt++) {
        #pragma unroll
        for (int nt = 0; nt < 4; nt++) {
            #pragma unroll
            for (int i = 0; i < 4; i++) {
                int m = bm + wm * 64 + mt * 16 + g + (i >> 1) * 8;
                int n = bn + wn * 32 + nt * 8 + 2 * t4 + (i & 1);
                float v = acc[mt][nt][i] + bias[n];
                if (MODE == 0) {
                    Cout[(size_t)m * CDIM + n] = v;
                } else {
                    int which = n / CDIM;
                    int c = n - which * CDIM;
                    int h = c >> 6;
                    int d = c & 63;
                    int b2 = m >> 10;
                    int t = m & 1023;
                    if (which == 0) {
                        size_t idx = (((size_t)(b2 * NH + h) * SEQ) + t) * HD + d;
                        ((__half*)g_q)[idx] = __float2half(v * QSCALE);
                    } else if (which == 1) {
                        size_t idx = (((size_t)(b2 * NH + h) * SEQ) + t) * HD + d;
                        ((__half*)g_k)[idx] = __float2half(v);
                    } else {
                        size_t idx = (((size_t)(b2 * NH + h) * HD) + d) * SEQ + t;
                        ((__half*)g_vT)[idx] = __float2half(v);
                    }
                }
            }
        }
    }
}

// ---------------------------------------------------------------------------
// Flash tile body (round-14 verbatim): fixed-shift log2 softmax, P in regs.
// ---------------------------------------------------------------------------
#define BQT 128
#define LDF 36
#define KVW (64 * LDF)
#define FST 3

__device__ __forceinline__ void flash_tile(int b, int h, int q0,
                                           const int* __restrict__ mask,
                                           uint32_t* smu, int tid)
{
    uint32_t* Ks = smu;                        // [FST][64][LDF]
    uint32_t* Vs = smu + FST * KVW;            // [FST][64][LDF]
    uint32_t* Ps = Vs + FST * KVW;             // [128][LDF]  (Q staging)
    float* maskf = (float*)(Ps + BQT * LDF);   // [FST][64]
    const uint32_t sKs = smem_u32(Ks);
    const uint32_t sVs = smem_u32(Vs);
    const uint32_t sPs = smem_u32(Ps);

    const uint32_t* Qp2 = g_q  + ((size_t)(b * NH + h) * SEQ) * (HD / 2);
    const uint32_t* Kp2 = g_k  + ((size_t)(b * NH + h) * SEQ) * (HD / 2);
    const uint32_t* Vt2 = g_vT + ((size_t)(b * NH + h) * HD) * (SEQ / 2);

    const int warp = tid >> 5;
    const int lane = tid & 31;
    const int g    = lane >> 2;
    const int t4   = lane & 3;

    const int lr    = lane & 7;
    const int rowAo = warp * 16 + ((lane >> 3) & 1) * 8 + lr;
    const int colAo = (lane >> 4) * 4;
    const int rowB4 = lr + ((lane >> 4) & 1) * 8;
    const int colB4 = ((lane >> 3) & 1) * 4;

    auto stage_kv = [&](int buf, int kt) {
        #pragma unroll
        for (int it = 0; it < 2; it++) {
            int i = tid + it * 256;
            int r = i >> 3, c = i & 7;
            cpa16(sKs + (uint32_t)(buf * KVW + r * LDF + c * 4) * 4,
                  &Kp2[(size_t)(kt * 64 + r) * 32 + c * 4]);
        }
        #pragma unroll
        for (int it = 0; it < 2; it++) {
            int i = tid + it * 256;
            int r = i >> 3, c = i & 7;
            cpa16(sVs + (uint32_t)(buf * KVW + r * LDF + c * 4) * 4,
                  &Vt2[(size_t)r * (SEQ / 2) + kt * 32 + c * 4]);
        }
        cpa_commit();
        if (tid < 64)
            maskf[buf * 64 + tid] = (mask[b * SEQ + kt * 64 + tid] == 0) ? -1e30f : MASKC;
    };

    #pragma unroll
    for (int it = 0; it < 4; it++) {
        int i = tid + it * 256;
        int r = i >> 3, c = i & 7;
        cpa16(sPs + (uint32_t)(r * LDF + c * 4) * 4,
              &Qp2[(size_t)(q0 + r) * 32 + c * 4]);
    }
    cpa_commit();
    stage_kv(0, 0);
    stage_kv(1, 1);
    cpa_wait<2>();
    __syncthreads();

    uint32_t qf[4][4];
    #pragma unroll
    for (int ks = 0; ks < 4; ks++)
        ldsm4(qf[ks], sPs + (uint32_t)(rowAo * LDF + ks * 8 + colAo) * 4);

    float l0 = 0.f, l1 = 0.f;
    float oacc[8][4];
    #pragma unroll
    for (int nt = 0; nt < 8; nt++)
        #pragma unroll
        for (int i = 0; i < 4; i++) oacc[nt][i] = 0.f;

    const int NT = SEQ / 64;
    int buf = 0;
    for (int kt = 0; kt < NT; kt++) {
        if (kt + 2 < NT) cpa_wait<1>(); else cpa_wait<0>();
        __syncthreads();

        if (kt + 2 < NT) {
            int nbuf = buf + 2; if (nbuf >= FST) nbuf -= FST;
            stage_kv(nbuf, kt + 2);
        }

        const uint32_t bK = sKs + (uint32_t)(buf * KVW) * 4;
        const uint32_t bV = sVs + (uint32_t)(buf * KVW) * 4;
        const float* mb = &maskf[buf * 64];

        float sacc[8][4];
        #pragma unroll
        for (int nt = 0; nt < 8; nt++)
            #pragma unroll
            for (int i = 0; i < 4; i++) sacc[nt][i] = 0.f;

        {
            uint32_t kb[2][4][4];
            #pragma unroll
            for (int nt2 = 0; nt2 < 4; nt2++)
                ldsm4(kb[0][nt2], bK + (uint32_t)((rowB4 + nt2 * 16) * LDF + colB4) * 4);

            #pragma unroll
            for (int ks = 0; ks < 4; ks++) {
                const int cur = ks & 1;
                if (ks < 3) {
                    const int kk2n = (ks + 1) * 8;
                    #pragma unroll
                    for (int nt2 = 0; nt2 < 4; nt2++)
                        ldsm4(kb[cur ^ 1][nt2],
                              bK + (uint32_t)((rowB4 + nt2 * 16) * LDF + kk2n + colB4) * 4);
                }
                #pragma unroll
                for (int nt = 0; nt < 8; nt++)
                    mma_f16(sacc[nt], qf[ks], &kb[cur][nt >> 1][(nt & 1) * 2]);
            }
        }

        uint32_t pa[4][4];
        #pragma unroll
        for (int nt = 0; nt < 8; nt++) {
            float ma  = mb[nt * 8 + 2 * t4];
            float mb2 = mb[nt * 8 + 2 * t4 + 1];
            float e0 = ex2f(sacc[nt][0] + ma);
            float e1 = ex2f(sacc[nt][1] + mb2);
            float e2 = ex2f(sacc[nt][2] + ma);
            float e3 = ex2f(sacc[nt][3] + mb2);
            l0 += e0 + e1;
            l1 += e2 + e3;
            const int ks = nt >> 1;
            const int sl = (nt & 1) * 2;
            pa[ks][sl + 0] = f2h2(e0, e1);
            pa[ks][sl + 1] = f2h2(e2, e3);
        }

        {
            uint32_t vb[2][4][4];
            #pragma unroll
            for (int nt2 = 0; nt2 < 4; nt2++)
                ldsm4(vb[0][nt2], bV + (uint32_t)((rowB4 + nt2 * 16) * LDF + colB4) * 4);

            #pragma unroll
            for (int ks = 0; ks < 4; ks++) {
                const int cur = ks & 1;
                if (ks < 3) {
                    const int kk2n = (ks + 1) * 8;
                    #pragma unroll
                    for (int nt2 = 0; nt2 < 4; nt2++)
                        ldsm4(vb[cur ^ 1][nt2],
                              bV + (uint32_t)((rowB4 + nt2 * 16) * LDF + kk2n + colB4) * 4);
                }
                #pragma unroll
                for (int nt = 0; nt < 8; nt++)
                    mma_f16(oacc[nt], pa[ks], &vb[cur][nt >> 1][(nt & 1) * 2]);
            }
        }

        buf++; if (buf >= FST) buf = 0;
    }

    {
        l0 += __shfl_xor_sync(0xffffffff, l0, 1);
        l0 += __shfl_xor_sync(0xffffffff, l0, 2);
        l1 += __shfl_xor_sync(0xffffffff, l1, 1);
        l1 += __shfl_xor_sync(0xffffffff, l1, 2);
        float inv0 = 1.f / l0;
        float inv1 = 1.f / l1;
        int r0 = q0 + warp * 16 + g;
        size_t base0 = ((size_t)(b * SEQ + r0))     * (CDIM / 2) + h * (HD / 2);
        size_t base1 = ((size_t)(b * SEQ + r0 + 8)) * (CDIM / 2) + h * (HD / 2);
        #pragma unroll
        for (int nt = 0; nt < 8; nt++) {
            g_att[base0 + nt * 4 + t4] = f2h2(oacc[nt][0] * inv0, oacc[nt][1] * inv0);
            g_att[base1 + nt * 4 + t4] = f2h2(oacc[nt][2] * inv1, oacc[nt][3] * inv1);
        }
    }
}

// ---------------------------------------------------------------------------
// Fused persistent kernel, PHASE-MAJOR claim order (fixes round-12 causality):
// claims 0..1151 = QKV (bm-major => batch-b done by wave ~b/2),
// claims 1152..1919 = flash (b-major), claims 1920..2303 = proj (b-major).
// Every consumer claim happens after ALL its producers are claimed.
// ---------------------------------------------------------------------------
__global__ __launch_bounds__(256, 2)
void fused(const float* __restrict__ b_attn, const float* __restrict__ b_proj,
           const int* __restrict__ mask, float* __restrict__ out)
{
    extern __shared__ uint32_t sm[];
    __shared__ int s_idx;
    const int tid = threadIdx.x;

    for (;;) {
        if (tid == 0) s_idx = atomicAdd(&g_ctr, 1);
        __syncthreads();
        int idx = s_idx;
        if (idx >= NTILE) break;

        if (idx < NQ) {
            // QKV tile (bm-major: batch b tiles are indices [b*144, (b+1)*144))
            int bm = idx / 18, bn = idx - bm * 18;
            gemm_tile<1>(bm * 128, bn * 128, b_attn, nullptr, sm, tid);
            __syncthreads();
            if (tid == 0) { __threadfence(); atomicExch(&g_qflag[bm * 18 + bn], 1); }
        } else if (idx < NQ + NF) {
            // flash tile
            int f = idx - NQ;
            int b = f / 96, r = f - b * 96;
            int h = r >> 3, q = r & 7;
            if (tid == 0) {
                int c = h >> 1;
                for (int i = 0; i < 8; i++) {
                    int base = (b * 8 + i) * 18;
                    wait_flag(&g_qflag[base + c]);
                    wait_flag(&g_qflag[base + 6 + c]);
                    wait_flag(&g_qflag[base + 12 + c]);
                }
                __threadfence();
            }
            __syncthreads();
            flash_tile(b, h, q * 128, mask, sm, tid);
            __syncthreads();
            if (tid == 0) { __threadfence(); atomicExch(&g_fflag[(b * NH + h) * 8 + q], 1); }
        } else {
            // proj tile
            int p = idx - NQ - NF;
            int bm = p / 6, bn = p - bm * 6;
            int b = bm >> 3, qb = bm & 7;
            if (tid == 0) {
                for (int hh = 0; hh < NH; hh++)
                    wait_flag(&g_fflag[(b * NH + hh) * 8 + qb]);
                __threadfence();
            }
            __syncthreads();
            gemm_tile<0>(bm * 128, bn * 128, b_proj, out, sm, tid);
        }
        __syncthreads();   // smem + s_idx safe before next claim
    }
}

// ---------------------------------------------------------------------------
extern "C" void kernel_launch(void* const* d_in, const int* in_sizes, int n_in,
                              void* d_out, int out_size)
{
    const float* x      = (const float*)d_in[0];
    const int*   amask  = (const int*)  d_in[1];
    const float* W_attn = (const float*)d_in[2];
    const float* b_attn = (const float*)d_in[3];
    const float* W_proj = (const float*)d_in[4];
    const float* b_proj = (const float*)d_in[5];
    float* out = (float*)d_out;

    // 0) prep: reset queue state; x -> half; W transposes (one launch)
    prep<<<XBLK + WABLK + WPBLK, 256>>>(x, W_attn, W_proj);

    // 1) fused persistent pipeline (phase-major claim order)
    {
        const int smem = 2 * GST * TW * (int)sizeof(uint32_t);   // 110592 B
        cudaFuncSetAttribute(fused, cudaFuncAttributeMaxDynamicSharedMemorySize, smem);
        fused<<<296, 256, smem>>>(b_attn, b_proj, amask, out);
    }
}

// round 17
// speedup vs baseline: 1.5320x; 1.5320x over previous
#include <cuda_runtime.h>
#include <cuda_fp16.h>
#include <math.h>
#include <stdint.h>

#define BATCH 8
#define SEQ   1024
#define CDIM  768
#define NH    12
#define HD    64
#define N3    (3*CDIM)

// Scratch: fp16 payloads stored in uint32 arrays.
__device__ uint32_t g_q  [BATCH*NH*SEQ*HD/2];   // [B,H,T,D] half, pre-scaled 0.125*log2e
__device__ uint32_t g_k  [BATCH*NH*SEQ*HD/2];   // [B,H,T,D] half
__device__ uint32_t g_vT [BATCH*NH*SEQ*HD/2];   // [B,H,D,T] half (transposed)
__device__ uint32_t g_att[BATCH*SEQ*CDIM/2];    // [B,T,C] half
__device__ uint32_t g_xc [BATCH*SEQ*CDIM/2];    // x in half
__device__ uint32_t g_wat[N3*CDIM/2];           // W_attn^T [N3][CDIM] half
__device__ uint32_t g_wpt[CDIM*CDIM/2];         // W_proj^T [CDIM][CDIM] half

// ---------------------------------------------------------------------------
// helpers
// ---------------------------------------------------------------------------
__device__ __forceinline__ uint32_t f2h2(float a, float b) {
    __half2 h = __floats2half2_rn(a, b);
    return *(uint32_t*)&h;
}
__device__ __forceinline__ float ex2f(float x) {
    float r; asm("ex2.approx.f32 %0, %1;" : "=f"(r) : "f"(x)); return r;
}

__device__ __forceinline__ void mma_f16(float* c, const uint32_t* a, const uint32_t* b) {
    asm volatile(
        "mma.sync.aligned.m16n8k16.row.col.f32.f16.f16.f32 "
        "{%0,%1,%2,%3}, {%4,%5,%6,%7}, {%8,%9}, {%0,%1,%2,%3};"
        : "+f"(c[0]), "+f"(c[1]), "+f"(c[2]), "+f"(c[3])
        : "r"(a[0]), "r"(a[1]), "r"(a[2]), "r"(a[3]), "r"(b[0]), "r"(b[1]));
}

__device__ __forceinline__ void ldsm4(uint32_t* r, uint32_t a) {
    asm volatile("ldmatrix.sync.aligned.m8n8.x4.shared.b16 {%0,%1,%2,%3}, [%4];"
        : "=r"(r[0]), "=r"(r[1]), "=r"(r[2]), "=r"(r[3]) : "r"(a));
}

__device__ __forceinline__ void cpa16(uint32_t saddr, const void* gaddr) {
    asm volatile("cp.async.cg.shared.global [%0], [%1], 16;" :: "r"(saddr), "l"(gaddr));
}
__device__ __forceinline__ void cpa_commit() { asm volatile("cp.async.commit_group;"); }
template<int NN> __device__ __forceinline__ void cpa_wait() {
    asm volatile("cp.async.wait_group %0;" :: "n"(NN));
}
__device__ __forceinline__ uint32_t smem_u32(const void* p) {
    return (uint32_t)__cvta_generic_to_shared(p);
}

// softmax constants (log2 domain)
#define QSCALE  0.1803368867f    // 0.125 * log2(e)
#define MASKC  -14.4269504089f   // -10 * log2(e)  (fixed shift, cancels in norm)

// ---------------------------------------------------------------------------
// Merged prep kernel: x->half convert + both weight transposes, one launch.
// ---------------------------------------------------------------------------
#define XN4     (BATCH*SEQ*CDIM/4)      // 1572864
#define XBLK    (XN4/256)               // 6144
#define WABLK   ((N3/32)*(CDIM/32))     // 1728
#define WPBLK   ((CDIM/32)*(CDIM/32))   // 576

__device__ __forceinline__ void transpose_body(const float* __restrict__ w, __half* wt,
                                               int K, int N, int bx, int by, int tid)
{
    __shared__ float t[32][33];
    int tx = tid & 31, ty = tid >> 5;   // 32 x 8
    int n0 = bx * 32, k0 = by * 32;
    #pragma unroll
    for (int i = 0; i < 32; i += 8)
        t[ty + i][tx] = w[(size_t)(k0 + ty + i) * N + n0 + tx];
    __syncthreads();
    #pragma unroll
    for (int i = 0; i < 32; i += 8)
        wt[(size_t)(n0 + ty + i) * K + k0 + tx] = __float2half(t[tx][ty + i]);
}

__global__ void prep(const float* __restrict__ x,
                     const float* __restrict__ wa,
                     const float* __restrict__ wp)
{
    int bid = blockIdx.x;
    int tid = threadIdx.x;
    if (bid < XBLK) {
        int i = bid * 256 + tid;
        float4 v = ((const float4*)x)[i];
        uint2 u = { f2h2(v.x, v.y), f2h2(v.z, v.w) };
        ((uint2*)g_xc)[i] = u;
    } else if (bid < XBLK + WABLK) {
        int bb = bid - XBLK;
        transpose_body(wa, (__half*)g_wat, CDIM, N3, bb % (N3/32), bb / (N3/32), tid);
    } else {
        int bb = bid - XBLK - WABLK;
        transpose_body(wp, (__half*)g_wpt, CDIM, CDIM, bb % (CDIM/32), bb / (CDIM/32), tid);
    }
}

// ---------------------------------------------------------------------------
// QKV GEMM: C[M,N3] = x @ Wa^T + bias. BM=128, BN=128, BK=64 halves.
// 8 warps (2x4), 64x32 per warp. 3-stage cp.async, frag double-buffering.
// Epilogue scatters half q(*QSCALE)/k/vT.
// ---------------------------------------------------------------------------
#define LD2 36
#define TW  (128 * LD2)
#define GST 3
#define GNC (CDIM / 64)   // 12 chunks

__global__ __launch_bounds__(256, 2)
void gemm_qkv(const float* __restrict__ bias)
{
    const uint32_t* A2 = g_xc;    // [M][K/2]
    const uint32_t* W2 = g_wat;   // [N][K/2]
    const int K2 = CDIM / 2;

    extern __shared__ uint32_t sm[];
    const uint32_t sAs = smem_u32(sm);
    const uint32_t sBs = smem_u32(sm + GST * TW);

    const int tid  = threadIdx.x;
    const int bm   = blockIdx.y * 128;
    const int bn   = blockIdx.x * 128;
    const int warp = tid >> 5;
    const int lane = tid & 31;
    const int wm   = warp & 1;
    const int wn   = warp >> 1;
    const int g    = lane >> 2;
    const int t4   = lane & 3;

    const int lr    = lane & 7;
    const int rowAo = wm * 64 + ((lane >> 3) & 1) * 8 + lr;
    const int colAo = (lane >> 4) * 4;
    const int rowB4 = wn * 32 + lr + ((lane >> 4) & 1) * 8;
    const int colB4 = ((lane >> 3) & 1) * 4;

    float acc[4][4][4];
    #pragma unroll
    for (int mt = 0; mt < 4; mt++)
        #pragma unroll
        for (int nt = 0; nt < 4; nt++)
            #pragma unroll
            for (int i = 0; i < 4; i++) acc[mt][nt][i] = 0.f;

    auto stage = [&](int buf, int k0w) {
        #pragma unroll
        for (int it = 0; it < 4; it++) {
            int i = tid + it * 256;
            int r = i >> 3, c = i & 7;
            cpa16(sAs + (uint32_t)(buf * TW + r * LD2 + c * 4) * 4,
                  &A2[(size_t)(bm + r) * K2 + k0w + c * 4]);
        }
        #pragma unroll
        for (int it = 0; it < 4; it++) {
            int i = tid + it * 256;
            int r = i >> 3, c = i & 7;
            cpa16(sBs + (uint32_t)(buf * TW + r * LD2 + c * 4) * 4,
                  &W2[(size_t)(bn + r) * K2 + k0w + c * 4]);
        }
        cpa_commit();
    };

    stage(0, 0);
    stage(1, 32);

    int buf = 0;
    for (int ck = 0; ck < GNC; ck++) {
        if (ck + 2 < GNC) cpa_wait<1>(); else cpa_wait<0>();   // race-safe tail
        __syncthreads();

        if (ck + 2 < GNC) {
            int nbuf = buf + 2; if (nbuf >= GST) nbuf -= GST;
            stage(nbuf, (ck + 2) * 32);
        }

        const uint32_t bA = sAs + (uint32_t)(buf * TW) * 4;
        const uint32_t bB = sBs + (uint32_t)(buf * TW) * 4;

        uint32_t a[2][4][4], b[2][2][4];
        #pragma unroll
        for (int mt = 0; mt < 4; mt++)
            ldsm4(a[0][mt], bA + (uint32_t)((rowAo + mt * 16) * LD2 + colAo) * 4);
        #pragma unroll
        for (int nt2 = 0; nt2 < 2; nt2++)
            ldsm4(b[0][nt2], bB + (uint32_t)((rowB4 + nt2 * 16) * LD2 + colB4) * 4);

        #pragma unroll
        for (int ks = 0; ks < 4; ks++) {
            const int cur = ks & 1;
            if (ks < 3) {
                const int kk2n = (ks + 1) * 8;
                #pragma unroll
                for (int mt = 0; mt < 4; mt++)
                    ldsm4(a[cur ^ 1][mt],
                          bA + (uint32_t)((rowAo + mt * 16) * LD2 + kk2n + colAo) * 4);
                #pragma unroll
                for (int nt2 = 0; nt2 < 2; nt2++)
                    ldsm4(b[cur ^ 1][nt2],
                          bB + (uint32_t)((rowB4 + nt2 * 16) * LD2 + kk2n + colB4) * 4);
            }
            #pragma unroll
            for (int mt = 0; mt < 4; mt++)
                #pragma unroll
                for (int nt = 0; nt < 4; nt++)
                    mma_f16(acc[mt][nt], a[cur][mt], &b[cur][nt >> 1][(nt & 1) * 2]);
        }

        buf++; if (buf >= GST) buf = 0;
    }

    #pragma unroll
    for (int mt = 0; mt < 4; mt++) {
        #pragma unroll
        for (int nt = 0; nt < 4; nt++) {
            #pragma unroll
            for (int i = 0; i < 4; i++) {
                int m = bm + wm * 64 + mt * 16 + g + (i >> 1) * 8;
                int n = bn + wn * 32 + nt * 8 + 2 * t4 + (i & 1);
                float v = acc[mt][nt][i] + bias[n];
                int which = n / CDIM;
                int c = n - which * CDIM;
                int h = c >> 6;
                int d = c & 63;
                int b2 = m >> 10;
                int t = m & 1023;
                if (which == 0) {
                    size_t idx = (((size_t)(b2 * NH + h) * SEQ) + t) * HD + d;
                    ((__half*)g_q)[idx] = __float2half(v * QSCALE);
                } else if (which == 1) {
                    size_t idx = (((size_t)(b2 * NH + h) * SEQ) + t) * HD + d;
                    ((__half*)g_k)[idx] = __float2half(v);
                } else {
                    size_t idx = (((size_t)(b2 * NH + h) * HD) + d) * SEQ + t;
                    ((__half*)g_vT)[idx] = __float2half(v);
                }
            }
        }
    }
}

// ---------------------------------------------------------------------------
// Proj GEMM: out = g_att @ Wp^T + bias. BM=128, BN=96 -> 512 tiles (vs 384)
// to cut wave quantization (296 slots): makespan 2 x 0.75-tiles vs 2 x 1.0.
// 8 warps in 4x2 grid, 32x48 per warp (mt=2, nt=6, 3 paired-ldsm4 B loads).
// ---------------------------------------------------------------------------
#define TWB96 (96 * LD2)

__global__ __launch_bounds__(256, 2)
void gemm_proj(const float* __restrict__ bias, float* __restrict__ Cout)
{
    const uint32_t* A2 = g_att;   // [M][K/2]
    const uint32_t* W2 = g_wpt;   // [N][K/2]
    const int K2 = CDIM / 2;

    extern __shared__ uint32_t sm[];
    const uint32_t sAs = smem_u32(sm);
    const uint32_t sBs = smem_u32(sm + GST * TW);   // A region sized as 128-row tiles

    const int tid  = threadIdx.x;
    const int bm   = blockIdx.y * 128;
    const int bn   = blockIdx.x * 96;
    const int warp = tid >> 5;
    const int lane = tid & 31;
    const int wm   = warp & 3;      // 0..3 -> 32-row slice
    const int wn   = warp >> 2;     // 0..1 -> 48-col slice
    const int g    = lane >> 2;
    const int t4   = lane & 3;

    const int lr    = lane & 7;
    const int rowAo = wm * 32 + ((lane >> 3) & 1) * 8 + lr;
    const int colAo = (lane >> 4) * 4;
    const int rowB4 = wn * 48 + lr + ((lane >> 4) & 1) * 8;
    const int colB4 = ((lane >> 3) & 1) * 4;

    float acc[2][6][4];
    #pragma unroll
    for (int mt = 0; mt < 2; mt++)
        #pragma unroll
        for (int nt = 0; nt < 6; nt++)
            #pragma unroll
            for (int i = 0; i < 4; i++) acc[mt][nt][i] = 0.f;

    auto stage = [&](int buf, int k0w) {
        #pragma unroll
        for (int it = 0; it < 4; it++) {           // A: 128 rows
            int i = tid + it * 256;
            int r = i >> 3, c = i & 7;
            cpa16(sAs + (uint32_t)(buf * TW + r * LD2 + c * 4) * 4,
                  &A2[(size_t)(bm + r) * K2 + k0w + c * 4]);
        }
        #pragma unroll
        for (int it = 0; it < 3; it++) {           // B: 96 rows
            int i = tid + it * 256;
            int r = i >> 3, c = i & 7;
            cpa16(sBs + (uint32_t)(buf * TWB96 + r * LD2 + c * 4) * 4,
                  &W2[(size_t)(bn + r) * K2 + k0w + c * 4]);
        }
        cpa_commit();
    };

    stage(0, 0);
    stage(1, 32);

    int buf = 0;
    for (int ck = 0; ck < GNC; ck++) {
        if (ck + 2 < GNC) cpa_wait<1>(); else cpa_wait<0>();   // race-safe tail
        __syncthreads();

        if (ck + 2 < GNC) {
            int nbuf = buf + 2; if (nbuf >= GST) nbuf -= GST;
            stage(nbuf, (ck + 2) * 32);
        }

        const uint32_t bA = sAs + (uint32_t)(buf * TW) * 4;
        const uint32_t bB = sBs + (uint32_t)(buf * TWB96) * 4;

        uint32_t a[2][2][4], b[2][3][4];
        #pragma unroll
        for (int mt = 0; mt < 2; mt++)
            ldsm4(a[0][mt], bA + (uint32_t)((rowAo + mt * 16) * LD2 + colAo) * 4);
        #pragma unroll
        for (int nt2 = 0; nt2 < 3; nt2++)
            ldsm4(b[0][nt2], bB + (uint32_t)((rowB4 + nt2 * 16) * LD2 + colB4) * 4);

        #pragma unroll
        for (int ks = 0; ks < 4; ks++) {
            const int cur = ks & 1;
            if (ks < 3) {
                const int kk2n = (ks + 1) * 8;
                #pragma unroll
                for (int mt = 0; mt < 2; mt++)
                    ldsm4(a[cur ^ 1][mt],
                          bA + (uint32_t)((rowAo + mt * 16) * LD2 + kk2n + colAo) * 4);
                #pragma unroll
                for (int nt2 = 0; nt2 < 3; nt2++)
                    ldsm4(b[cur ^ 1][nt2],
                          bB + (uint32_t)((rowB4 + nt2 * 16) * LD2 + kk2n + colB4) * 4);
            }
            #pragma unroll
            for (int mt = 0; mt < 2; mt++)
                #pragma unroll
                for (int nt = 0; nt < 6; nt++)
                    mma_f16(acc[mt][nt], a[cur][mt], &b[cur][nt >> 1][(nt & 1) * 2]);
        }

        buf++; if (buf >= GST) buf = 0;
    }

    #pragma unroll
    for (int mt = 0; mt < 2; mt++) {
        #pragma unroll
        for (int nt = 0; nt < 6; nt++) {
            #pragma unroll
            for (int i = 0; i < 4; i++) {
                int m = bm + wm * 32 + mt * 16 + g + (i >> 1) * 8;
                int n = bn + wn * 48 + nt * 8 + 2 * t4 + (i & 1);
                Cout[(size_t)m * CDIM + n] = acc[mt][nt][i] + bias[n];
            }
        }
    }
}

// ---------------------------------------------------------------------------
// Flash attention (round-14 verbatim): fp16 mma + ldmatrix, 3-stage K/V pipe,
// fixed-shift log2-domain softmax, P passed in registers (c->a repack).
// ---------------------------------------------------------------------------
#define BQT 128
#define LDF 36
#define KVW (64 * LDF)
#define FST 3

__global__ __launch_bounds__(256, 2)
void flash_attn(const int* __restrict__ mask)
{
    extern __shared__ uint32_t smu[];
    uint32_t* Ks = smu;                        // [FST][64][LDF]
    uint32_t* Vs = smu + FST * KVW;            // [FST][64][LDF]
    uint32_t* Ps = Vs + FST * KVW;             // [128][LDF]  (Q staging only)
    float* maskf = (float*)(Ps + BQT * LDF);   // [FST][64]
    const uint32_t sKs = smem_u32(Ks);
    const uint32_t sVs = smem_u32(Vs);
    const uint32_t sPs = smem_u32(Ps);

    const int b  = blockIdx.z;
    const int h  = blockIdx.y;
    const int q0 = blockIdx.x * BQT;

    const uint32_t* Qp2 = g_q  + ((size_t)(b * NH + h) * SEQ) * (HD / 2);
    const uint32_t* Kp2 = g_k  + ((size_t)(b * NH + h) * SEQ) * (HD / 2);
    const uint32_t* Vt2 = g_vT + ((size_t)(b * NH + h) * HD) * (SEQ / 2);

    const int tid  = threadIdx.x;
    const int warp = tid >> 5;
    const int lane = tid & 31;
    const int g    = lane >> 2;
    const int t4   = lane & 3;

    const int lr    = lane & 7;
    const int rowAo = warp * 16 + ((lane >> 3) & 1) * 8 + lr;
    const int colAo = (lane >> 4) * 4;
    const int rowB4 = lr + ((lane >> 4) & 1) * 8;
    const int colB4 = ((lane >> 3) & 1) * 4;

    auto stage_kv = [&](int buf, int kt) {
        #pragma unroll
        for (int it = 0; it < 2; it++) {
            int i = tid + it * 256;
            int r = i >> 3, c = i & 7;
            cpa16(sKs + (uint32_t)(buf * KVW + r * LDF + c * 4) * 4,
                  &Kp2[(size_t)(kt * 64 + r) * 32 + c * 4]);
        }
        #pragma unroll
        for (int it = 0; it < 2; it++) {
            int i = tid + it * 256;
            int r = i >> 3, c = i & 7;
            cpa16(sVs + (uint32_t)(buf * KVW + r * LDF + c * 4) * 4,
                  &Vt2[(size_t)r * (SEQ / 2) + kt * 32 + c * 4]);
        }
        cpa_commit();
        if (tid < 64)
            maskf[buf * 64 + tid] = (mask[b * SEQ + kt * 64 + tid] == 0) ? -1e30f : MASKC;
    };

    #pragma unroll
    for (int it = 0; it < 4; it++) {
        int i = tid + it * 256;
        int r = i >> 3, c = i & 7;
        cpa16(sPs + (uint32_t)(r * LDF + c * 4) * 4,
              &Qp2[(size_t)(q0 + r) * 32 + c * 4]);
    }
    cpa_commit();
    stage_kv(0, 0);
    stage_kv(1, 1);
    cpa_wait<2>();     // Q group complete
    __syncthreads();

    uint32_t qf[4][4];
    #pragma unroll
    for (int ks = 0; ks < 4; ks++)
        ldsm4(qf[ks], sPs + (uint32_t)(rowAo * LDF + ks * 8 + colAo) * 4);

    float l0 = 0.f, l1 = 0.f;
    float oacc[8][4];
    #pragma unroll
    for (int nt = 0; nt < 8; nt++)
        #pragma unroll
        for (int i = 0; i < 4; i++) oacc[nt][i] = 0.f;

    const int NT = SEQ / 64;
    int buf = 0;
    for (int kt = 0; kt < NT; kt++) {
        if (kt + 2 < NT) cpa_wait<1>(); else cpa_wait<0>();   // race-safe tail
        __syncthreads();

        if (kt + 2 < NT) {
            int nbuf = buf + 2; if (nbuf >= FST) nbuf -= FST;
            stage_kv(nbuf, kt + 2);
        }

        const uint32_t bK = sKs + (uint32_t)(buf * KVW) * 4;
        const uint32_t bV = sVs + (uint32_t)(buf * KVW) * 4;
        const float* mb = &maskf[buf * 64];

        // ---- S = Q @ K^T ----
        float sacc[8][4];
        #pragma unroll
        for (int nt = 0; nt < 8; nt++)
            #pragma unroll
            for (int i = 0; i < 4; i++) sacc[nt][i] = 0.f;

        {
            uint32_t kb[2][4][4];
            #pragma unroll
            for (int nt2 = 0; nt2 < 4; nt2++)
                ldsm4(kb[0][nt2], bK + (uint32_t)((rowB4 + nt2 * 16) * LDF + colB4) * 4);

            #pragma unroll
            for (int ks = 0; ks < 4; ks++) {
                const int cur = ks & 1;
                if (ks < 3) {
                    const int kk2n = (ks + 1) * 8;
                    #pragma unroll
                    for (int nt2 = 0; nt2 < 4; nt2++)
                        ldsm4(kb[cur ^ 1][nt2],
                              bK + (uint32_t)((rowB4 + nt2 * 16) * LDF + kk2n + colB4) * 4);
                }
                #pragma unroll
                for (int nt = 0; nt < 8; nt++)
                    mma_f16(sacc[nt], qf[ks], &kb[cur][nt >> 1][(nt & 1) * 2]);
            }
        }

        // ---- fixed-shift exp; pack P directly into A-fragments (registers) ----
        uint32_t pa[4][4];
        #pragma unroll
        for (int nt = 0; nt < 8; nt++) {
            float ma  = mb[nt * 8 + 2 * t4];
            float mb2 = mb[nt * 8 + 2 * t4 + 1];
            float e0 = ex2f(sacc[nt][0] + ma);
            float e1 = ex2f(sacc[nt][1] + mb2);
            float e2 = ex2f(sacc[nt][2] + ma);
            float e3 = ex2f(sacc[nt][3] + mb2);
            l0 += e0 + e1;
            l1 += e2 + e3;
            const int ks = nt >> 1;
            const int sl = (nt & 1) * 2;
            pa[ks][sl + 0] = f2h2(e0, e1);
            pa[ks][sl + 1] = f2h2(e2, e3);
        }

        // ---- O += P @ V ----
        {
            uint32_t vb[2][4][4];
            #pragma unroll
            for (int nt2 = 0; nt2 < 4; nt2++)
                ldsm4(vb[0][nt2], bV + (uint32_t)((rowB4 + nt2 * 16) * LDF + colB4) * 4);

            #pragma unroll
            for (int ks = 0; ks < 4; ks++) {
                const int cur = ks & 1;
                if (ks < 3) {
                    const int kk2n = (ks + 1) * 8;
                    #pragma unroll
                    for (int nt2 = 0; nt2 < 4; nt2++)
                        ldsm4(vb[cur ^ 1][nt2],
                              bV + (uint32_t)((rowB4 + nt2 * 16) * LDF + kk2n + colB4) * 4);
                }
                #pragma unroll
                for (int nt = 0; nt < 8; nt++)
                    mma_f16(oacc[nt], pa[ks], &vb[cur][nt >> 1][(nt & 1) * 2]);
            }
        }

        buf++; if (buf >= FST) buf = 0;
    }

    // ---- epilogue: finish deferred l reduction, normalize, write g_att ----
    {
        l0 += __shfl_xor_sync(0xffffffff, l0, 1);
        l0 += __shfl_xor_sync(0xffffffff, l0, 2);
        l1 += __shfl_xor_sync(0xffffffff, l1, 1);
        l1 += __shfl_xor_sync(0xffffffff, l1, 2);
        float inv0 = 1.f / l0;
        float inv1 = 1.f / l1;
        int r0 = q0 + warp * 16 + g;
        size_t base0 = ((size_t)(b * SEQ + r0))     * (CDIM / 2) + h * (HD / 2);
        size_t base1 = ((size_t)(b * SEQ + r0 + 8)) * (CDIM / 2) + h * (HD / 2);
        #pragma unroll
        for (int nt = 0; nt < 8; nt++) {
            g_att[base0 + nt * 4 + t4] = f2h2(oacc[nt][0] * inv0, oacc[nt][1] * inv0);
            g_att[base1 + nt * 4 + t4] = f2h2(oacc[nt][2] * inv1, oacc[nt][3] * inv1);
        }
    }
}

// ---------------------------------------------------------------------------
extern "C" void kernel_launch(void* const* d_in, const int* in_sizes, int n_in,
                              void* d_out, int out_size)
{
    const float* x      = (const float*)d_in[0];
    const int*   amask  = (const int*)  d_in[1];
    const float* W_attn = (const float*)d_in[2];
    const float* b_attn = (const float*)d_in[3];
    const float* W_proj = (const float*)d_in[4];
    const float* b_proj = (const float*)d_in[5];
    float* out = (float*)d_out;

    // 0) merged prep: x -> half, W_attn^T, W_proj^T (one launch)
    prep<<<XBLK + WABLK + WPBLK, 256>>>(x, W_attn, W_proj);

    // 1) QKV GEMM (BM=128, BN=128) -> half q/k/vT
    {
        const int smem = 2 * GST * TW * (int)sizeof(uint32_t);
        cudaFuncSetAttribute(gemm_qkv,
                             cudaFuncAttributeMaxDynamicSharedMemorySize, smem);
        dim3 grid(N3 / 128, (BATCH * SEQ) / 128);
        gemm_qkv<<<grid, 256, smem>>>(b_attn);
    }

    // 2) flash attention (P in registers) -> half g_att
    {
        int smem = (2 * FST * KVW + BQT * LDF + FST * 64 + 64) * (int)sizeof(uint32_t);
        cudaFuncSetAttribute(flash_attn, cudaFuncAttributeMaxDynamicSharedMemorySize, smem);
        dim3 grid(SEQ / BQT, NH, BATCH);
        flash_attn<<<grid, 256, smem>>>(amask);
    }

    // 3) proj GEMM (BM=128, BN=96: 512 tiles -> better wave packing on 296 slots)
    {
        const int smem = GST * (TW + TWB96) * (int)sizeof(uint32_t);
        cudaFuncSetAttribute(gemm_proj,
                             cudaFuncAttributeMaxDynamicSharedMemorySize, smem);
        dim3 grid(CDIM / 96, (BATCH * SEQ) / 128);
        gemm_proj<<<grid, 256, smem>>>(b_proj, out);
    }
}